// round 1
// baseline (speedup 1.0000x reference)
#include <cuda_runtime.h>
#include <cstring>
#include <cmath>

// ============================================================================
// CPAB activation (difw Tessellation, NC=16 cells, RADIUS=3, 10x5 integration)
//
// Math reduction: the reference's sort/unsort is an identity composition around
// a purely element-wise map, so out[n,c] = f_c(x[n,c]). Conditioned on the
// cell/branch decisions, every integration step is affine in phi, so f_c is
// piecewise-LINEAR in x0. We therefore:
//   1) (host)  reproduce B_BASIS = last 15 rows of Q from the Householder LQ
//              of the 17x32 constraint matrix (LAPACK dgesdd Path 4t leaves
//              VT[m:n] = Q[m:n] untouched by the SVD of L17).
//   2) (gpu)   build a 1025-sample LUT of f_c per channel with the EXACT
//              reference integrator (closed-form + Euler fallback).
//   3) (gpu)   stream all 33.5M elements through a lerp of the LUT
//              (channel-blocked, LUT slice in shared memory). HBM-bound.
// ============================================================================

#define M_SAMP      1024
#define CH_PER_BLK  8
#define MAX_C       256

struct BParam { float B[32][15]; };

// LUT scratch: 256 channels x (M_SAMP+1) samples of the final output value.
__device__ float g_tab[MAX_C * (M_SAMP + 1)];

// ----------------------------------------------------------------------------
// Host: B_BASIS via Householder LQ of the CPA constraint matrix (float64),
// matching LAPACK DGELQF + DORGLQ (which is what numpy's dgesdd Path 4t
// produces for the null-space rows Vt[17:32]).
// ----------------------------------------------------------------------------
static void compute_basis(float Bout[32][15]) {
    const int nc = 16;
    const int m = nc + 1;      // 17
    const int n = 2 * nc;      // 32
    double A[17][32];
    std::memset(A, 0, sizeof(A));
    for (int k = 1; k < nc; k++) {
        double xk = (double)k / (double)nc;
        A[k - 1][2 * (k - 1)]     =  xk;
        A[k - 1][2 * (k - 1) + 1] =  1.0;
        A[k - 1][2 * k]           = -xk;
        A[k - 1][2 * k + 1]       = -1.0;
    }
    A[nc - 1][1]         = 1.0;  // b_0 = 0
    A[nc][2 * (nc - 1)]  = 1.0;  // a_{15} + b_{15} = 0
    A[nc][2 * nc - 1]    = 1.0;

    double tau[17];
    // Unblocked LQ (DGELQ2): row reflectors applied from the right.
    for (int i = 0; i < m; i++) {
        double xn2 = 0.0;
        for (int j = i + 1; j < n; j++) xn2 += A[i][j] * A[i][j];
        double alpha = A[i][i];
        if (xn2 == 0.0) { tau[i] = 0.0; continue; }
        double beta = -copysign(sqrt(alpha * alpha + xn2), alpha);
        tau[i] = (beta - alpha) / beta;
        double s = 1.0 / (alpha - beta);
        for (int j = i + 1; j < n; j++) A[i][j] *= s;   // v stored; v_i = 1
        A[i][i] = beta;
        for (int r = i + 1; r < m; r++) {
            double w = A[r][i];
            for (int j = i + 1; j < n; j++) w += A[r][j] * A[i][j];
            w *= tau[i];
            A[r][i] -= w;
            for (int j = i + 1; j < n; j++) A[r][j] -= w * A[i][j];
        }
    }
    // Rows m..n-1 of Q = H(m)...H(1):  q = H1(H2(...(Hm e_j))).
    for (int t = 0; t < 15; t++) {
        double q[32];
        for (int j = 0; j < n; j++) q[j] = 0.0;
        q[m + t] = 1.0;
        for (int i = m - 1; i >= 0; i--) {
            if (tau[i] == 0.0) continue;
            double w = q[i];
            for (int j = i + 1; j < n; j++) w += A[i][j] * q[j];
            w *= tau[i];
            q[i] -= w;
            for (int j = i + 1; j < n; j++) q[j] -= w * A[i][j];
        }
        for (int j = 0; j < n; j++) Bout[j][t] = (float)q[j];  // B_BASIS[j][t]
    }
}

// ----------------------------------------------------------------------------
// Device
// ----------------------------------------------------------------------------
__device__ __forceinline__ int cellf(float x) {
    int c = __float2int_rd(x * 16.0f);   // floor, matches jnp.floor + cast
    return min(max(c, 0), 15);
}

// One block per channel: compute a,b from theta @ B^T, then the exact
// reference integration at M_SAMP+1 grid points xs = i/M_SAMP.
__global__ void build_tab_kernel(const float* __restrict__ theta,
                                 const int* __restrict__ time_p,
                                 BParam Bp) {
    __shared__ float sa[16], sb[16], sE[16], sK[16];
    int c = blockIdx.x;
    int tid = threadIdx.x;

    if (tid < 32) {
        float acc = 0.0f;
        #pragma unroll
        for (int t = 0; t < 15; t++) acc += theta[c * 15 + t] * Bp.B[tid][t];
        if (tid & 1) sb[tid >> 1] = acc;  // A[:,1::2]
        else         sa[tid >> 1] = acc;  // A[:,0::2]
    }
    __syncthreads();

    float tm  = (float)(*time_p);   // low word of int scalar (1)
    float dt  = tm / 10.0f;         // time / NSTEPS1
    float ddt = dt / 5.0f;          // dt / NSTEPS2

    if (tid < 16) {
        float a = sa[tid], b = sb[tid];
        float eta = expf(dt * a);
        bool  nz  = fabsf(a) > 1e-7f;
        sE[tid] = nz ? eta : 1.0f;
        sK[tid] = nz ? (b / a) * (eta - 1.0f) : b * dt;
    }
    __syncthreads();

    for (int i = tid; i <= M_SAMP; i += blockDim.x) {
        float phi = (float)i / (float)M_SAMP;
        #pragma unroll 1
        for (int s = 0; s < 10; s++) {
            int   c0 = cellf(phi);
            float pc = fmaf(sE[c0], phi, sK[c0]);   // closed-form psi
            if (cellf(pc) == c0) {
                phi = pc;                            // stayed in cell
            } else {
                float p = phi;                       // 5 Euler substeps
                #pragma unroll
                for (int e = 0; e < 5; e++) {
                    int   cc = cellf(p);
                    float v  = fmaf(sa[cc], p, sb[cc]);
                    p = fmaf(ddt, v, p);
                }
                phi = p;
            }
        }
        g_tab[c * (M_SAMP + 1) + i] = fmaf(phi, 6.0f, -3.0f);  // *2R - R
    }
}

// Channel-blocked streaming pass: 8 channels/block, LUT slice in shared.
// Warp covers 4 rows x 8 channels -> full 32B sectors on x and out.
__global__ void cpab_main_kernel(const float* __restrict__ x,
                                 float* __restrict__ out,
                                 int N, int C) {
    __shared__ float s_tab[CH_PER_BLK * (M_SAMP + 1)];  // 32.8 KB
    int c0 = blockIdx.x * CH_PER_BLK;

    for (int i = threadIdx.x; i < CH_PER_BLK * (M_SAMP + 1); i += blockDim.x)
        s_tab[i] = g_tab[c0 * (M_SAMP + 1) + i];
    __syncthreads();

    int lc  = threadIdx.x & (CH_PER_BLK - 1);
    int rof = threadIdx.x >> 3;            // 0..31
    const float* tb = s_tab + lc * (M_SAMP + 1);
    int c = c0 + lc;

    int rows_per = (N + gridDim.y - 1) / gridDim.y;
    int r0 = blockIdx.y * rows_per;
    int r1 = min(r0 + rows_per, N);

    #pragma unroll 4
    for (int r = r0 + rof; r < r1; r += 32) {
        size_t idx = (size_t)r * C + c;
        float xv = x[idx];
        float xs = (xv + 3.0f) / 6.0f;
        float res;
        if (xs >= 1.0f || xs <= 0.0f) {
            res = xv;                       // out-of-domain: identity
        } else {
            float t = xs * (float)M_SAMP;
            int   i = (int)t;
            i = min(i, M_SAMP - 1);
            float fr = t - (float)i;
            float y0 = tb[i];
            float y1 = tb[i + 1];
            res = fmaf(y1 - y0, fr, y0);
        }
        out[idx] = res;
    }
}

// ----------------------------------------------------------------------------
// Launch: inputs = [x, edge_index, edge_attr, batch, time, theta]
// output = concat(out[N,C], theta[C,15]) as float32
// ----------------------------------------------------------------------------
extern "C" void kernel_launch(void* const* d_in, const int* in_sizes, int n_in,
                              void* d_out, int out_size) {
    const float* x      = (const float*)d_in[0];
    const int*   time_p = (const int*)d_in[4];   // int scalar, low word valid
    const float* theta  = (const float*)d_in[5];

    int C = in_sizes[5] / 15;   // 256
    int N = in_sizes[0] / C;    // 131072

    BParam Bp;
    compute_basis(Bp.B);        // pure host math, deterministic, ~us

    build_tab_kernel<<<C, 256>>>(theta, time_p, Bp);

    dim3 grid(C / CH_PER_BLK, 64);
    cpab_main_kernel<<<grid, 256>>>(x, (float*)d_out, N, C);

    // theta passthrough (second tuple element)
    cudaMemcpyAsync((float*)d_out + (size_t)N * C, theta,
                    (size_t)C * 15 * sizeof(float),
                    cudaMemcpyDeviceToDevice);
}

// round 3
// speedup vs baseline: 1.3264x; 1.3264x over previous
#include <cuda_runtime.h>
#include <cstring>
#include <cmath>

// ============================================================================
// CPAB activation (difw Tessellation, NC=16 cells, RADIUS=3, 10x5 integration)
//
// out[n,c] = f_c(x[n,c]) where f_c is piecewise-LINEAR in x0 (all integration
// steps are affine conditioned on cell/branch decisions). Strategy:
//   1) host: B_BASIS = last 15 rows of Q from Householder LQ of the 17x32
//      constraint matrix (matches numpy dgesdd Path 4t null-space rows).
//   2) gpu:  build 1025-sample LUT of f_c per channel with the exact
//      reference integrator; also emit the theta passthrough.
//   3) gpu:  float4-vectorized streaming lerp pass (8 ch/block, LUT in smem).
// ============================================================================

#define M_SAMP      1024
#define TAB_W       (M_SAMP + 1)
#define CH_PER_BLK  8
#define MAX_C       256

struct BParam { float B[32][15]; };

__device__ float g_tab[MAX_C * TAB_W];

// ----------------------------------------------------------------------------
// Host: B_BASIS via Householder LQ (float64), matching LAPACK DGELQF/DORGLQ.
// ----------------------------------------------------------------------------
static void compute_basis(float Bout[32][15]) {
    const int nc = 16;
    const int m = nc + 1;      // 17
    const int n = 2 * nc;      // 32
    double A[17][32];
    std::memset(A, 0, sizeof(A));
    for (int k = 1; k < nc; k++) {
        double xk = (double)k / (double)nc;
        A[k - 1][2 * (k - 1)]     =  xk;
        A[k - 1][2 * (k - 1) + 1] =  1.0;
        A[k - 1][2 * k]           = -xk;
        A[k - 1][2 * k + 1]       = -1.0;
    }
    A[nc - 1][1]         = 1.0;
    A[nc][2 * (nc - 1)]  = 1.0;
    A[nc][2 * nc - 1]    = 1.0;

    double tau[17];
    for (int i = 0; i < m; i++) {
        double xn2 = 0.0;
        for (int j = i + 1; j < n; j++) xn2 += A[i][j] * A[i][j];
        double alpha = A[i][i];
        if (xn2 == 0.0) { tau[i] = 0.0; continue; }
        double beta = -copysign(sqrt(alpha * alpha + xn2), alpha);
        tau[i] = (beta - alpha) / beta;
        double s = 1.0 / (alpha - beta);
        for (int j = i + 1; j < n; j++) A[i][j] *= s;
        A[i][i] = beta;
        for (int r = i + 1; r < m; r++) {
            double w = A[r][i];
            for (int j = i + 1; j < n; j++) w += A[r][j] * A[i][j];
            w *= tau[i];
            A[r][i] -= w;
            for (int j = i + 1; j < n; j++) A[r][j] -= w * A[i][j];
        }
    }
    for (int t = 0; t < 15; t++) {
        double q[32];
        for (int j = 0; j < n; j++) q[j] = 0.0;
        q[m + t] = 1.0;
        for (int i = m - 1; i >= 0; i--) {
            if (tau[i] == 0.0) continue;
            double w = q[i];
            for (int j = i + 1; j < n; j++) w += A[i][j] * q[j];
            w *= tau[i];
            q[i] -= w;
            for (int j = i + 1; j < n; j++) q[j] -= w * A[i][j];
        }
        for (int j = 0; j < n; j++) Bout[j][t] = (float)q[j];
    }
}

// ----------------------------------------------------------------------------
// Device
// ----------------------------------------------------------------------------
__device__ __forceinline__ int cellf(float x) {
    int c = __float2int_rd(x * 16.0f);
    return min(max(c, 0), 15);
}

// One block per channel: a,b from theta @ B^T, then exact reference
// integration at TAB_W grid points. Also emits theta passthrough rows.
__global__ void build_tab_kernel(const float* __restrict__ theta,
                                 const int* __restrict__ time_p,
                                 float* __restrict__ theta_out,
                                 BParam Bp) {
    __shared__ float sa[16], sb[16], sE[16], sK[16];
    int c = blockIdx.x;
    int tid = threadIdx.x;

    if (tid < 32) {
        float acc = 0.0f;
        #pragma unroll
        for (int t = 0; t < 15; t++) acc += theta[c * 15 + t] * Bp.B[tid][t];
        if (tid & 1) sb[tid >> 1] = acc;
        else         sa[tid >> 1] = acc;
    }
    // theta passthrough: block c copies its 15 floats
    if (tid >= 32 && tid < 32 + 15)
        theta_out[c * 15 + (tid - 32)] = theta[c * 15 + (tid - 32)];
    __syncthreads();

    float tm  = (float)(*time_p);
    float dt  = tm / 10.0f;
    float ddt = dt / 5.0f;

    if (tid < 16) {
        float a = sa[tid], b = sb[tid];
        float eta = expf(dt * a);
        bool  nz  = fabsf(a) > 1e-7f;
        sE[tid] = nz ? eta : 1.0f;
        sK[tid] = nz ? (b / a) * (eta - 1.0f) : b * dt;
    }
    __syncthreads();

    for (int i = tid; i <= M_SAMP; i += blockDim.x) {
        float phi = (float)i / (float)M_SAMP;
        #pragma unroll 1
        for (int s = 0; s < 10; s++) {
            int   c0 = cellf(phi);
            float pc = fmaf(sE[c0], phi, sK[c0]);
            if (cellf(pc) == c0) {
                phi = pc;
            } else {
                float p = phi;
                #pragma unroll
                for (int e = 0; e < 5; e++) {
                    int   cc = cellf(p);
                    float v  = fmaf(sa[cc], p, sb[cc]);
                    p = fmaf(ddt, v, p);
                }
                phi = p;
            }
        }
        g_tab[c * TAB_W + i] = fmaf(phi, 6.0f, -3.0f);
    }
}

// ----------------------------------------------------------------------------
// Main pass: float4-vectorized. Block handles 8 channels; thread (q = tid&1,
// row = tid>>1) processes channels [c0 + q*4, c0 + q*4 + 4) of one row per
// iteration via a single LDG.128 / STG.128. Lane pairs cover 32B sectors.
// ----------------------------------------------------------------------------
__device__ __forceinline__ float lerp_tab(const float* __restrict__ tb, float xv) {
    float xs = (xv + 3.0f) * (1.0f / 6.0f);
    if (xs >= 1.0f || xs <= 0.0f) return xv;
    float t = xs * (float)M_SAMP;
    int   i = min((int)t, M_SAMP - 1);
    float fr = t - (float)i;
    float y0 = tb[i];
    float y1 = tb[i + 1];
    return fmaf(y1 - y0, fr, y0);
}

__global__ void __launch_bounds__(256) cpab_main_kernel(
        const float4* __restrict__ x4,
        float4* __restrict__ out4,
        int N, int C4) {
    __shared__ float s_tab[CH_PER_BLK * TAB_W];   // 32.8 KB

    int c0 = blockIdx.x * CH_PER_BLK;             // first channel of block
    for (int i = threadIdx.x; i < CH_PER_BLK * TAB_W; i += blockDim.x)
        s_tab[i] = g_tab[c0 * TAB_W + i];
    __syncthreads();

    int q   = threadIdx.x & 1;                    // which float4 of the 8 ch
    int row = threadIdx.x >> 1;                   // 0..127
    const float* tb = s_tab + q * 4 * TAB_W;

    int vbase = blockIdx.x * 2 + q;               // float4 column index

    int rows_per = (N + gridDim.y - 1) / gridDim.y;
    int r0 = blockIdx.y * rows_per;
    int r1 = min(r0 + rows_per, N);

    #pragma unroll 4
    for (int r = r0 + row; r < r1; r += 128) {
        size_t idx = (size_t)r * C4 + vbase;
        float4 v = x4[idx];
        float4 o;
        o.x = lerp_tab(tb + 0 * TAB_W, v.x);
        o.y = lerp_tab(tb + 1 * TAB_W, v.y);
        o.z = lerp_tab(tb + 2 * TAB_W, v.z);
        o.w = lerp_tab(tb + 3 * TAB_W, v.w);
        out4[idx] = o;
    }
}

// ----------------------------------------------------------------------------
// Launch: inputs = [x, edge_index, edge_attr, batch, time, theta]
// output = concat(out[N,C], theta[C,15]) as float32
// ----------------------------------------------------------------------------
extern "C" void kernel_launch(void* const* d_in, const int* in_sizes, int n_in,
                              void* d_out, int out_size) {
    const float* x      = (const float*)d_in[0];
    const int*   time_p = (const int*)d_in[4];
    const float* theta  = (const float*)d_in[5];

    int C = in_sizes[5] / 15;   // 256
    int N = in_sizes[0] / C;    // 131072

    BParam Bp;
    compute_basis(Bp.B);

    build_tab_kernel<<<C, 256>>>(theta, time_p,
                                 (float*)d_out + (size_t)N * C, Bp);

    dim3 grid(C / CH_PER_BLK, 64);
    cpab_main_kernel<<<grid, 256>>>((const float4*)x, (float4*)d_out,
                                    N, C / 4);
}